// round 5
// baseline (speedup 1.0000x reference)
#include <cuda_runtime.h>
#include <cstdint>

// ============================================================================
// CausalAttentionHead: B=8, S=2048, E=768, H=128, fp32.
//   Kernel 1: fused masked QKV projection (q pre-scaled by 1/sqrt(H))
//   Kernel 2: fp32 flash attention (causal, online softmax)
// Both kernels use packed fma.rn.f32x2 (Blackwell f32x2 pipe) for 2x fp32 MAC.
// ============================================================================

#define NB 8
#define NS 2048
#define NE 768
#define NH 128
#define MROWS (NB * NS)

typedef unsigned long long u64;
#define DEV_INLINE __device__ __forceinline__

// -------------------- packed f32x2 helpers --------------------
DEV_INLINE u64 ffma2(u64 a, u64 b, u64 c) {
    u64 d;
    asm("fma.rn.f32x2 %0, %1, %2, %3;" : "=l"(d) : "l"(a), "l"(b), "l"(c));
    return d;
}
DEV_INLINE u64 fmul2(u64 a, u64 b) {
    u64 d;
    asm("mul.rn.f32x2 %0, %1, %2;" : "=l"(d) : "l"(a), "l"(b));
    return d;
}
DEV_INLINE u64 pack2(float lo, float hi) {
    u64 r;
    asm("mov.b64 %0, {%1, %2};" : "=l"(r) : "f"(lo), "f"(hi));
    return r;
}
DEV_INLINE float2 unpack2(u64 v) {
    float2 f;
    asm("mov.b64 {%0, %1}, %2;" : "=f"(f.x), "=f"(f.y) : "l"(v));
    return f;
}

// FMA-pipe exp (avoids MUFU throughput wall). e^x for x <= 0 (finite).
// 2^t = 2^n * poly(f), degree-6 Taylor of 2^f on [0,1): rel err ~1e-5.
DEV_INLINE float fast_exp(float x) {
    float t = x * 1.4426950408889634f;
    t = fmaxf(t, -125.0f);
    float n = floorf(t);
    float f = t - n;
    float p = 1.5403530393381606e-4f;
    p = fmaf(p, f, 1.3333558146428443e-3f);
    p = fmaf(p, f, 9.6181291076284770e-3f);
    p = fmaf(p, f, 5.5504108664821580e-2f);
    p = fmaf(p, f, 2.4022650695910070e-1f);
    p = fmaf(p, f, 6.9314718055994530e-1f);
    p = fmaf(p, f, 1.0f);
    return __int_as_float(((int)n + 127) << 23) * p;
}

// -------------------- scratch (no allocation allowed) --------------------
__device__ float g_q[MROWS * NH];
__device__ float g_k[MROWS * NH];
__device__ float g_v[MROWS * NH];

// ============================================================================
// Kernel 1: QKV projection. out[z][row, col] = sum_e (X[row,e]*mask[row]) * W_z[col,e]
// Grid: (16384/128, 3).  BM=128 rows, BN=128 cols, BK=32.  8x8 thread tile.
// f32x2 packs the reduction dim (even/odd-k partial sums) -> zero pack overhead.
// ============================================================================
__global__ __launch_bounds__(256, 1)
void qkv_kernel(const float* __restrict__ X, const float* __restrict__ pm,
                const float* __restrict__ Wq, const float* __restrict__ Wk,
                const float* __restrict__ Wv) {
    __shared__ float sX[128 * 36];   // 32 + 4 pad (odd*4 bank skew, 16B-aligned rows)
    __shared__ float sW[128 * 36];

    const int tid  = threadIdx.x;
    const int row0 = blockIdx.x * 128;
    const int z    = blockIdx.y;
    const float* W = (z == 0) ? Wq : (z == 1) ? Wk : Wv;
    float* dst     = (z == 0) ? g_q : (z == 1) ? g_k : g_v;

    const int rg = tid >> 4;   // 0..15: rows rg*8 + i
    const int cg = tid & 15;   // 0..15: cols cg + 16*j (consecutive lanes -> consecutive rows)

    // fill-loop geometry: slice t handles row lr[t] = (tid + t*256)>>3, cols lc..lc+3
    const int lr0 = tid >> 3;          // base row for t=0 (0..31)
    const int lc  = (tid & 7) << 2;    // fixed col offset within 32-wide chunk
    float mreg[4];
    const float* xrow[4];
    const float* wrow[4];
    float* sxrow[4];
    float* swrow[4];
#pragma unroll
    for (int t = 0; t < 4; t++) {
        int r   = lr0 + t * 32;
        mreg[t] = pm[row0 + r];                     // hoisted: 1 LDG per slice, not 24
        xrow[t] = X + (u64)(row0 + r) * NE + lc;
        wrow[t] = W + (u64)r * NE + lc;
        sxrow[t] = sX + r * 36 + lc;
        swrow[t] = sW + r * 36 + lc;
    }

    u64 acc[8][8];
#pragma unroll
    for (int i = 0; i < 8; i++)
#pragma unroll
        for (int j = 0; j < 8; j++) acc[i][j] = 0ULL;

    for (int kc = 0; kc < 24; kc++) {
        const int k0 = kc * 32;
        __syncthreads();
#pragma unroll
        for (int t = 0; t < 4; t++) {
            float  m  = mreg[t];
            float4 xv = *(const float4*)(xrow[t] + k0);
            xv.x *= m; xv.y *= m; xv.z *= m; xv.w *= m;
            *(float4*)sxrow[t] = xv;
            *(float4*)swrow[t] = *(const float4*)(wrow[t] + k0);
        }
        __syncthreads();
#pragma unroll 4
        for (int kp = 0; kp < 16; kp++) {
            u64 a[8], b[8];
#pragma unroll
            for (int i = 0; i < 8; i++) a[i] = *(const u64*)(sX + (rg * 8 + i) * 36 + 2 * kp);
#pragma unroll
            for (int j = 0; j < 8; j++) b[j] = *(const u64*)(sW + (cg + 16 * j) * 36 + 2 * kp);
#pragma unroll
            for (int i = 0; i < 8; i++)
#pragma unroll
                for (int j = 0; j < 8; j++)
                    acc[i][j] = ffma2(a[i], b[j], acc[i][j]);
        }
    }

    const float scale = (z == 0) ? 0.08838834764831845f : 1.0f;  // 1/sqrt(128) folded into q
#pragma unroll
    for (int i = 0; i < 8; i++) {
        int gr = row0 + rg * 8 + i;
#pragma unroll
        for (int j = 0; j < 8; j++) {
            float2 f = unpack2(acc[i][j]);
            dst[(u64)gr * NH + cg + 16 * j] = (f.x + f.y) * scale;
        }
    }
}

// ============================================================================
// Kernel 2: causal flash attention, fp32. Grid (32 qtiles, 8 batches), 256 thr.
// BM=BN=64, D=128. Score phase: 4q x 4k per thread, f32x2 over d.
// PV phase: 4q x 8d per thread, f32x2 over d. Softmax: shuffle row-reduce,
// FMA-pipe exp in all 256 threads, per-row state in smem (warp-exclusive rows).
// ============================================================================
#define QKV_STRIDE 132   // 128 + 4 pad; rows 16B aligned; 4-bank skew
#define SS_STRIDE  66
#define ATTN_SMEM_FLOATS (3 * 64 * QKV_STRIDE + 64 * SS_STRIDE + 3 * 64)
#define ATTN_SMEM_BYTES  (ATTN_SMEM_FLOATS * 4)

__global__ __launch_bounds__(256, 1)
void attn_kernel(float* __restrict__ out) {
    extern __shared__ float smf[];
    float* sQ = smf;
    float* sK = sQ + 64 * QKV_STRIDE;
    float* sV = sK + 64 * QKV_STRIDE;
    float* sS = sV + 64 * QKV_STRIDE;
    float* sM = sS + 64 * SS_STRIDE;
    float* sL = sM + 64;
    float* sC = sL + 64;

    const int tid  = threadIdx.x;
    const int qt   = 31 - blockIdx.x;       // heavy tiles first (LPT scheduling)
    const int b    = blockIdx.y;
    const int q0   = qt * 64;
    const int base = b << 11;               // b * 2048

    // load Q tile (pre-scaled by 1/sqrt(H))
    {
        const float* qptr = g_q + (u64)(base + q0) * NH;
#pragma unroll
        for (int t = 0; t < 8; t++) {
            int u = tid + t * 256;
            int r = u >> 5;
            int c = (u & 31) << 2;
            *(float4*)(sQ + r * QKV_STRIDE + c) = *(const float4*)(qptr + r * NH + c);
        }
    }
    if (tid < 64) { sM[tid] = -3.0e38f; sL[tid] = 0.0f; }

    const int qgs = tid >> 4;   // 0..15: rows qgs*4 + i (16-lane-group-exclusive)
    const int kgs = tid & 15;   // score: keys kgs + 16*j ; PV: d-pairs 2*kgs + 32*j2

    u64 accO[4][4];
#pragma unroll
    for (int i = 0; i < 4; i++)
#pragma unroll
        for (int j = 0; j < 4; j++) accO[i][j] = 0ULL;

    for (int kb = 0; kb <= qt; kb++) {
        const int k0 = kb * 64;
        __syncthreads();   // protect sK/sV/sS vs previous PV reads
        {
            const float* kptr = g_k + (u64)(base + k0) * NH;
            const float* vptr = g_v + (u64)(base + k0) * NH;
#pragma unroll
            for (int t = 0; t < 8; t++) {
                int u = tid + t * 256;
                int r = u >> 5;
                int c = (u & 31) << 2;
                *(float4*)(sK + r * QKV_STRIDE + c) = *(const float4*)(kptr + r * NH + c);
                *(float4*)(sV + r * QKV_STRIDE + c) = *(const float4*)(vptr + r * NH + c);
            }
        }
        __syncthreads();

        // ---- scores: S[r][c] = sum_d q*k (f32x2 over d) ----
        u64 accS[4][4];
#pragma unroll
        for (int i = 0; i < 4; i++)
#pragma unroll
            for (int j = 0; j < 4; j++) accS[i][j] = 0ULL;
#pragma unroll 4
        for (int dp = 0; dp < 64; dp++) {
            u64 a[4], k4[4];
#pragma unroll
            for (int i = 0; i < 4; i++)
                a[i] = *(const u64*)(sQ + (qgs * 4 + i) * QKV_STRIDE + 2 * dp);
#pragma unroll
            for (int j = 0; j < 4; j++)
                k4[j] = *(const u64*)(sK + (kgs + 16 * j) * QKV_STRIDE + 2 * dp);
#pragma unroll
            for (int i = 0; i < 4; i++)
#pragma unroll
                for (int j = 0; j < 4; j++)
                    accS[i][j] = ffma2(a[i], k4[j], accS[i][j]);
        }
        float s[4][4];
#pragma unroll
        for (int i = 0; i < 4; i++)
#pragma unroll
            for (int j = 0; j < 4; j++) {
                float2 f = unpack2(accS[i][j]);
                s[i][j] = f.x + f.y;
            }
        if (kb == qt) {   // diagonal block: per-element causal mask
#pragma unroll
            for (int i = 0; i < 4; i++)
#pragma unroll
                for (int j = 0; j < 4; j++)
                    if (kgs + 16 * j > qgs * 4 + i) s[i][j] = -1.0e30f;
        }

        // ---- online softmax: shuffle reductions within 16-lane row group ----
#pragma unroll
        for (int i = 0; i < 4; i++) {
            const int row = qgs * 4 + i;
            float rmax = fmaxf(fmaxf(s[i][0], s[i][1]), fmaxf(s[i][2], s[i][3]));
#pragma unroll
            for (int off = 8; off >= 1; off >>= 1)
                rmax = fmaxf(rmax, __shfl_xor_sync(0xffffffffu, rmax, off));
            float mo = sM[row];               // row owned by this 16-lane group only
            float mn = fmaxf(mo, rmax);
            float co = fast_exp(mo - mn);
            float rs = 0.0f;
#pragma unroll
            for (int j = 0; j < 4; j++) {
                float p = fast_exp(s[i][j] - mn);
                sS[row * SS_STRIDE + kgs + 16 * j] = p;
                rs += p;
            }
#pragma unroll
            for (int off = 8; off >= 1; off >>= 1)
                rs += __shfl_xor_sync(0xffffffffu, rs, off);
            if (kgs == 0) {                   // shuffle above orders reads before this write
                sL[row] = sL[row] * co + rs;
                sM[row] = mn;
                sC[row] = co;
            }
        }
        __syncthreads();

        // ---- PV: O[r][d] = O*corr + sum_k P[r][k]*V[k][d] (f32x2 over d) ----
#pragma unroll
        for (int i = 0; i < 4; i++) {
            float c = sC[qgs * 4 + i];
            u64 c2 = pack2(c, c);
#pragma unroll
            for (int j2 = 0; j2 < 4; j2++) accO[i][j2] = fmul2(accO[i][j2], c2);
        }
#pragma unroll 4
        for (int kj = 0; kj < 64; kj++) {
            u64 v[4];
#pragma unroll
            for (int j2 = 0; j2 < 4; j2++)
                v[j2] = *(const u64*)(sV + kj * QKV_STRIDE + 2 * kgs + 32 * j2);
#pragma unroll
            for (int i = 0; i < 4; i++) {
                float p = sS[(qgs * 4 + i) * SS_STRIDE + kj];
                u64 p2 = pack2(p, p);
#pragma unroll
                for (int j2 = 0; j2 < 4; j2++)
                    accO[i][j2] = ffma2(p2, v[j2], accO[i][j2]);
            }
        }
    }

    // ---- finalize: O /= l, write out ----
#pragma unroll
    for (int i = 0; i < 4; i++) {
        const int row = qgs * 4 + i;
        float inv = 1.0f / sL[row];
        u64 inv2 = pack2(inv, inv);
        float* optr = out + (u64)(base + q0 + row) * NH;
#pragma unroll
        for (int j2 = 0; j2 < 4; j2++) {
            u64 r = fmul2(accO[i][j2], inv2);
            *(u64*)(optr + 2 * kgs + 32 * j2) = r;
        }
    }
}

// ============================================================================
extern "C" void kernel_launch(void* const* d_in, const int* in_sizes, int n_in,
                              void* d_out, int out_size) {
    const float* X  = (const float*)d_in[0];
    const float* pm = (const float*)d_in[1];
    const float* Wq = (const float*)d_in[2];
    const float* Wk = (const float*)d_in[3];
    const float* Wv = (const float*)d_in[4];
    float* out = (float*)d_out;

    static bool attr_set = false;   // host-side config, identical every call
    if (!attr_set) {
        cudaFuncSetAttribute(attn_kernel, cudaFuncAttributeMaxDynamicSharedMemorySize,
                             ATTN_SMEM_BYTES);
        attr_set = true;
    }

    qkv_kernel<<<dim3(MROWS / 128, 3, 1), 256>>>(X, pm, Wq, Wk, Wv);
    attn_kernel<<<dim3(32, 8, 1), 256, ATTN_SMEM_BYTES>>>(out);
}